// round 12
// baseline (speedup 1.0000x reference)
#include <cuda_runtime.h>
#include <cuda_bf16.h>

#define C               128
#define NPRED           8
#define WARPS_PER_BLOCK 4
#define THREADS         (WARPS_PER_BLOCK * 32)
#define ROWS_PER_TILE   (WARPS_PER_BLOCK * 2)   // 2 rows per warp
#define BLOCKS_PER_SM   10   // 128thr x 10 = 1280 thr/SM (62.5% occ), 51-reg cap

// Statically-initialized scratch (no allocations allowed). Finalizing block
// resets it -> deterministic across graph replays.
__device__ int      g_max_bits    = (int)0x80000000;
__device__ unsigned g_blocks_done = 0;

__device__ __forceinline__ int f2ord(float x) {
    int i = __float_as_int(x);
    return (i >= 0) ? i : (i ^ 0x7FFFFFFF);
}
__device__ __forceinline__ float ord2f(int i) {
    return __int_as_float((i >= 0) ? i : (i ^ 0x7FFFFFFF));
}

__device__ __forceinline__ float comp(float4 q, int j) {
    return (j == 0) ? q.x : (j == 1) ? q.y : (j == 2) ? q.z : q.w;
}

__device__ __forceinline__ void prefetch_l2(const void* p) {
    asm volatile("prefetch.global.L2 [%0];" :: "l"(p));
}

// Process one tile of ROWS_PER_TILE rows.
__device__ __forceinline__ void process_tile(
    int tile, const float* const* preds, const int* __restrict__ targets,
    float* __restrict__ out, int warp, int lane, int grp, int lig,
    float& acc_max7)
{
    const long long row = (long long)tile * ROWS_PER_TILE + warp * 2 + grp;

    const int t = targets[row];          // group-uniform
    const int tsrc = (grp << 4) + ((t & 63) >> 2);
    const int tj   = t & 3;
    const bool thi = (t >= 64);

    const long long base = row * (long long)C + (long long)(lig << 2);

    float margins[NPRED];
    float rowmax7 = -3.4e38f;

    // Two batches of 4 predictors: only 8 float4 (32 regs) of payload live at
    // once. L2 prefetch of batch 1 alongside batch 0's loads keeps 16
    // line-requests/warp in flight without register cost.
#pragma unroll
    for (int b = 0; b < 2; b++) {
        float4 va[4], vb[4];
#pragma unroll
        for (int i = 0; i < 4; i++)
            va[i] = __ldcs(reinterpret_cast<const float4*>(preds[b * 4 + i] + base));
#pragma unroll
        for (int i = 0; i < 4; i++)
            vb[i] = __ldcs(reinterpret_cast<const float4*>(preds[b * 4 + i] + base + 64));

        if (b == 0) {
#pragma unroll
            for (int i = 0; i < 4; i++) {
                prefetch_l2(preds[4 + i] + base);
                prefetch_l2(preds[4 + i] + base + 64);
            }
        }

#pragma unroll
        for (int i = 0; i < 4; i++) {
            const int p = b * 4 + i;
            const float4 qa = va[i];
            const float4 qb = vb[i];

            // local multiset top-2 of this lane's 8 values
            float a1 = fmaxf(qa.x, qa.y), a2 = fminf(qa.x, qa.y);
            float a3 = fmaxf(qa.z, qa.w), a4 = fminf(qa.z, qa.w);
            float m1a = fmaxf(a1, a3);
            float m2a = fmaxf(fminf(a1, a3), fmaxf(a2, a4));

            float b1 = fmaxf(qb.x, qb.y), b2 = fminf(qb.x, qb.y);
            float b3 = fmaxf(qb.z, qb.w), b4 = fminf(qb.z, qb.w);
            float m1b = fmaxf(b1, b3);
            float m2b = fmaxf(fminf(b1, b3), fmaxf(b2, b4));

            float m1 = fmaxf(m1a, m1b);
            float m2 = fmaxf(fminf(m1a, m1b), fmaxf(m2a, m2b));

            // target value: candidate from owning half, broadcast from owning lane
            float cand = thi ? comp(qb, tj) : comp(qa, tj);
            float tv = __shfl_sync(0xFFFFFFFFu, cand, tsrc);

            // 16-lane multiset top-2 butterfly (stays within the group)
#pragma unroll
            for (int off = 8; off > 0; off >>= 1) {
                float o1 = __shfl_xor_sync(0xFFFFFFFFu, m1, off);
                float o2 = __shfl_xor_sync(0xFFFFFFFFu, m2, off);
                float n1 = fmaxf(m1, o1);
                float n2 = fmaxf(fminf(m1, o1), fmaxf(m2, o2));
                m1 = n1; m2 = n2;
            }

            margins[p] = (tv == m1) ? (m1 - m2) : 0.0f;
            if (p < 7) rowmax7 = fmaxf(rowmax7, m1);
        }
        asm volatile("" ::: "memory");  // keep batches from being hoisted
    }

    // ---- lane-parallel softmax over the 8 margins, T = 2.0 ----
    // Each lane exponentiates only its own (lig-selected) margin — 1 MUFU
    // instead of 8, and no live e[8] array (register savings for the 51-reg
    // cap). Butterfly offsets 1/2/4 keep lanes 0-7 and 8-15 in disjoint
    // subgroups, so the high lanes never contaminate the writers.
    float mm = margins[0];
#pragma unroll
    for (int p = 1; p < NPRED; p++) mm = fmaxf(mm, margins[p]);

    float mv = margins[0];
    mv = (lig == 1) ? margins[1] : mv;
    mv = (lig == 2) ? margins[2] : mv;
    mv = (lig == 3) ? margins[3] : mv;
    mv = (lig == 4) ? margins[4] : mv;
    mv = (lig == 5) ? margins[5] : mv;
    mv = (lig == 6) ? margins[6] : mv;
    mv = (lig >= 7) ? margins[7] : mv;

    const float ex = __expf((mv - mm) * 0.5f);
    float s = ex;
    s += __shfl_xor_sync(0xFFFFFFFFu, s, 1);
    s += __shfl_xor_sync(0xFFFFFFFFu, s, 2);
    s += __shfl_xor_sync(0xFFFFFFFFu, s, 4);

    if (lig < NPRED) {
        __stcs(&out[1 + row * NPRED + lig], ex / s);
    }

    acc_max7 = fmaxf(acc_max7, rowmax7);
}

__global__ __launch_bounds__(THREADS, BLOCKS_PER_SM)
void tw_kernel(const float* __restrict__ p0, const float* __restrict__ p1,
               const float* __restrict__ p2, const float* __restrict__ p3,
               const float* __restrict__ p4, const float* __restrict__ p5,
               const float* __restrict__ p6, const float* __restrict__ p7,
               const int*   __restrict__ targets,
               float* __restrict__ out,   // out[0]=max_preds, out+1 = [N,8]
               int extra)  // first `extra` blocks also handle tile gridDim.x + bid
{
    const int warp = threadIdx.x >> 5;
    const int lane = threadIdx.x & 31;
    const int grp  = lane >> 4;
    const int lig  = lane & 15;

    const float* preds[NPRED] = {p0, p1, p2, p3, p4, p5, p6, p7};

    float acc_max7 = -3.4e38f;

    // Primary tile (every block), then a tail tile for the first `extra`
    // blocks — these sit in wave 1, so their 2nd tile overlaps later waves
    // instead of forming an under-filled final wave.
    process_tile(blockIdx.x, preds, targets, out, warp, lane, grp, lig, acc_max7);
    if (blockIdx.x < extra) {
        process_tile(gridDim.x + blockIdx.x, preds, targets, out,
                     warp, lane, grp, lig, acc_max7);
    }

    // combine the warp's two groups, then block reduce -> 1 atomic/block
    acc_max7 = fmaxf(acc_max7, __shfl_xor_sync(0xFFFFFFFFu, acc_max7, 16));

    __shared__ float sm[WARPS_PER_BLOCK];
    if (lane == 0) sm[warp] = acc_max7;
    __syncthreads();
    if (threadIdx.x == 0) {
        float bm = sm[0];
#pragma unroll
        for (int i = 1; i < WARPS_PER_BLOCK; i++) bm = fmaxf(bm, sm[i]);
        atomicMax(&g_max_bits, f2ord(bm));
        __threadfence();
        unsigned prev = atomicAdd(&g_blocks_done, 1u);
        if (prev == gridDim.x - 1u) {
            out[0] = ord2f(g_max_bits);
            g_max_bits    = (int)0x80000000;
            g_blocks_done = 0;
        }
    }
}

extern "C" void kernel_launch(void* const* d_in, const int* in_sizes, int n_in,
                              void* d_out, int out_size)
{
    const float* p0  = (const float*)d_in[0];
    const float* p1  = (const float*)d_in[1];
    const float* p2  = (const float*)d_in[2];
    const float* p3  = (const float*)d_in[3];
    const float* p4  = (const float*)d_in[4];
    const float* p5  = (const float*)d_in[5];
    const float* p6  = (const float*)d_in[6];
    const float* mim = (const float*)d_in[7];
    const int*   tg  = (const int*)d_in[8];

    const int N = in_sizes[8];
    float* out = (float*)d_out;

    static int sm_count = 0;             // attribute query only (no allocation)
    if (sm_count == 0) {
        cudaDeviceGetAttribute(&sm_count, cudaDevAttrMultiProcessorCount, 0);
        if (sm_count <= 0) sm_count = 152;
    }

    const int ntiles = (N + ROWS_PER_TILE - 1) / ROWS_PER_TILE;
    const int slots  = sm_count * BLOCKS_PER_SM;

    int grid, extra;
    if (ntiles > slots) {
        const int full_waves = ntiles / slots;
        grid  = full_waves * slots;      // whole waves only
        extra = ntiles - grid;           // tail tiles folded into wave 1
    } else {
        grid  = ntiles;
        extra = 0;
    }

    tw_kernel<<<grid, THREADS>>>(p0, p1, p2, p3, p4, p5, p6, mim, tg, out, extra);
}

// round 13
// speedup vs baseline: 1.0056x; 1.0056x over previous
#include <cuda_runtime.h>
#include <cuda_bf16.h>

#define C               128
#define NPRED           8
#define WARPS_PER_BLOCK 4
#define THREADS         (WARPS_PER_BLOCK * 32)
#define ROWS_PER_TILE   (WARPS_PER_BLOCK * 2)   // 2 rows per warp
#define BLOCKS_PER_SM   10   // 128thr x 10 = 1280 thr/SM: measured BW peak (~55% occ)

// Statically-initialized scratch (no allocations allowed). Finalizing block
// resets it -> deterministic across graph replays.
__device__ int      g_max_bits    = (int)0x80000000;
__device__ unsigned g_blocks_done = 0;

__device__ __forceinline__ int f2ord(float x) {
    int i = __float_as_int(x);
    return (i >= 0) ? i : (i ^ 0x7FFFFFFF);
}
__device__ __forceinline__ float ord2f(int i) {
    return __int_as_float((i >= 0) ? i : (i ^ 0x7FFFFFFF));
}

__device__ __forceinline__ float comp(float4 q, int j) {
    return (j == 0) ? q.x : (j == 1) ? q.y : (j == 2) ? q.z : q.w;
}

// Process one tile of ROWS_PER_TILE rows.
__device__ __forceinline__ void process_tile(
    int tile, const float* const* preds, const int* __restrict__ targets,
    float* __restrict__ out, int warp, int lane, int grp, int lig,
    float& acc_max7)
{
    const long long row = (long long)tile * ROWS_PER_TILE + warp * 2 + grp;

    const int t = targets[row];          // group-uniform
    const int tsrc = (grp << 4) + ((t & 63) >> 2);
    const int tj   = t & 3;
    const bool thi = (t >= 64);

    const long long base = row * (long long)C + (long long)(lig << 2);

    float margins[NPRED];
    float rowmax7 = -3.4e38f;

    // Two batches of 4 predictors: only 8 float4 (32 regs) of payload live at
    // once. At 55% occupancy the inter-batch latency is covered by warp-level
    // parallelism (prefetch removed: it only cost LSU issue slots here).
#pragma unroll
    for (int b = 0; b < 2; b++) {
        float4 va[4], vb[4];
#pragma unroll
        for (int i = 0; i < 4; i++)
            va[i] = __ldcs(reinterpret_cast<const float4*>(preds[b * 4 + i] + base));
#pragma unroll
        for (int i = 0; i < 4; i++)
            vb[i] = __ldcs(reinterpret_cast<const float4*>(preds[b * 4 + i] + base + 64));

#pragma unroll
        for (int i = 0; i < 4; i++) {
            const int p = b * 4 + i;
            const float4 qa = va[i];
            const float4 qb = vb[i];

            // local multiset top-2 of this lane's 8 values
            float a1 = fmaxf(qa.x, qa.y), a2 = fminf(qa.x, qa.y);
            float a3 = fmaxf(qa.z, qa.w), a4 = fminf(qa.z, qa.w);
            float m1a = fmaxf(a1, a3);
            float m2a = fmaxf(fminf(a1, a3), fmaxf(a2, a4));

            float b1 = fmaxf(qb.x, qb.y), b2 = fminf(qb.x, qb.y);
            float b3 = fmaxf(qb.z, qb.w), b4 = fminf(qb.z, qb.w);
            float m1b = fmaxf(b1, b3);
            float m2b = fmaxf(fminf(b1, b3), fmaxf(b2, b4));

            float m1 = fmaxf(m1a, m1b);
            float m2 = fmaxf(fminf(m1a, m1b), fmaxf(m2a, m2b));

            // target value: candidate from owning half, broadcast from owning lane
            float cand = thi ? comp(qb, tj) : comp(qa, tj);
            float tv = __shfl_sync(0xFFFFFFFFu, cand, tsrc);

            // 16-lane multiset top-2 butterfly (stays within the group)
#pragma unroll
            for (int off = 8; off > 0; off >>= 1) {
                float o1 = __shfl_xor_sync(0xFFFFFFFFu, m1, off);
                float o2 = __shfl_xor_sync(0xFFFFFFFFu, m2, off);
                float n1 = fmaxf(m1, o1);
                float n2 = fmaxf(fminf(m1, o1), fmaxf(m2, o2));
                m1 = n1; m2 = n2;
            }

            margins[p] = (tv == m1) ? (m1 - m2) : 0.0f;
            if (p < 7) rowmax7 = fmaxf(rowmax7, m1);
        }
        asm volatile("" ::: "memory");  // keep batches from being hoisted
    }

    // ---- lane-parallel softmax over the 8 margins, T = 2.0 ----
    // Each lane exponentiates only its own (lig-selected) margin — 1 MUFU
    // instead of 8, no live e[8] array. Butterfly offsets 1/2/4 keep lanes
    // 0-7 and 8-15 in disjoint subgroups.
    float mm = margins[0];
#pragma unroll
    for (int p = 1; p < NPRED; p++) mm = fmaxf(mm, margins[p]);

    float mv = margins[0];
    mv = (lig == 1) ? margins[1] : mv;
    mv = (lig == 2) ? margins[2] : mv;
    mv = (lig == 3) ? margins[3] : mv;
    mv = (lig == 4) ? margins[4] : mv;
    mv = (lig == 5) ? margins[5] : mv;
    mv = (lig == 6) ? margins[6] : mv;
    mv = (lig >= 7) ? margins[7] : mv;

    const float ex = __expf((mv - mm) * 0.5f);
    float s = ex;
    s += __shfl_xor_sync(0xFFFFFFFFu, s, 1);
    s += __shfl_xor_sync(0xFFFFFFFFu, s, 2);
    s += __shfl_xor_sync(0xFFFFFFFFu, s, 4);

    if (lig < NPRED) {
        __stcs(&out[1 + row * NPRED + lig], ex / s);
    }

    acc_max7 = fmaxf(acc_max7, rowmax7);
}

__global__ __launch_bounds__(THREADS, BLOCKS_PER_SM)
void tw_kernel(const float* __restrict__ p0, const float* __restrict__ p1,
               const float* __restrict__ p2, const float* __restrict__ p3,
               const float* __restrict__ p4, const float* __restrict__ p5,
               const float* __restrict__ p6, const float* __restrict__ p7,
               const int*   __restrict__ targets,
               float* __restrict__ out,   // out[0]=max_preds, out+1 = [N,8]
               int extra)  // first `extra` blocks also handle tile gridDim.x + bid
{
    const int warp = threadIdx.x >> 5;
    const int lane = threadIdx.x & 31;
    const int grp  = lane >> 4;
    const int lig  = lane & 15;

    const float* preds[NPRED] = {p0, p1, p2, p3, p4, p5, p6, p7};

    float acc_max7 = -3.4e38f;

    // Primary tile (every block), then a tail tile for the first `extra`
    // blocks — these sit in wave 1, so their 2nd tile overlaps later waves
    // instead of forming an under-filled final wave.
    process_tile(blockIdx.x, preds, targets, out, warp, lane, grp, lig, acc_max7);
    if (blockIdx.x < extra) {
        process_tile(gridDim.x + blockIdx.x, preds, targets, out,
                     warp, lane, grp, lig, acc_max7);
    }

    // combine the warp's two groups, then block reduce -> 1 atomic/block
    acc_max7 = fmaxf(acc_max7, __shfl_xor_sync(0xFFFFFFFFu, acc_max7, 16));

    __shared__ float sm[WARPS_PER_BLOCK];
    if (lane == 0) sm[warp] = acc_max7;
    __syncthreads();
    if (threadIdx.x == 0) {
        float bm = sm[0];
#pragma unroll
        for (int i = 1; i < WARPS_PER_BLOCK; i++) bm = fmaxf(bm, sm[i]);
        atomicMax(&g_max_bits, f2ord(bm));
        __threadfence();
        unsigned prev = atomicAdd(&g_blocks_done, 1u);
        if (prev == gridDim.x - 1u) {
            out[0] = ord2f(g_max_bits);
            g_max_bits    = (int)0x80000000;
            g_blocks_done = 0;
        }
    }
}

extern "C" void kernel_launch(void* const* d_in, const int* in_sizes, int n_in,
                              void* d_out, int out_size)
{
    const float* p0  = (const float*)d_in[0];
    const float* p1  = (const float*)d_in[1];
    const float* p2  = (const float*)d_in[2];
    const float* p3  = (const float*)d_in[3];
    const float* p4  = (const float*)d_in[4];
    const float* p5  = (const float*)d_in[5];
    const float* p6  = (const float*)d_in[6];
    const float* mim = (const float*)d_in[7];
    const int*   tg  = (const int*)d_in[8];

    const int N = in_sizes[8];
    float* out = (float*)d_out;

    static int sm_count = 0;             // attribute query only (no allocation)
    if (sm_count == 0) {
        cudaDeviceGetAttribute(&sm_count, cudaDevAttrMultiProcessorCount, 0);
        if (sm_count <= 0) sm_count = 152;
    }

    const int ntiles = (N + ROWS_PER_TILE - 1) / ROWS_PER_TILE;
    const int slots  = sm_count * BLOCKS_PER_SM;

    int grid, extra;
    if (ntiles > slots) {
        const int full_waves = ntiles / slots;
        grid  = full_waves * slots;      // whole waves only
        extra = ntiles - grid;           // tail tiles folded into wave 1
    } else {
        grid  = ntiles;
        extra = 0;
    }

    tw_kernel<<<grid, THREADS>>>(p0, p1, p2, p3, p4, p5, p6, mim, tg, out, extra);
}